// round 15
// baseline (speedup 1.0000x reference)
#include <cuda_runtime.h>
#include <mma.h>
#include <cstdint>

using namespace nvcuda;

#define NN 50000
#define NE 312500
#define WD 256
#define MROWS 50048          // 391 * 128
#define NCHUNK 49            // ceil(50000/1024)

// ---- scratch (device globals; no allocation allowed) ----
__device__ int   g_deg[NN];
__device__ int   g_cursor[NN];
__device__ float g_dinv[NN];
__device__ int   g_off[NN + 1];
__device__ int   g_srcs[NE];
__device__ float g_h[MROWS * WD];     // h = x @ W^T, 51.2 MB — L2-resident
__device__ int   g_csum[NCHUNK];
__device__ int   g_is64;

// ---------------------------------------------------------------------------
// init + index-dtype detection (reference declares int64 edge_index; JAX
// without x64 silently emits int32 — 64 in-range int64 reads are conclusive)
// ---------------------------------------------------------------------------
__global__ void k_init(const void* __restrict__ ei) {
    int i = blockIdx.x * blockDim.x + threadIdx.x;
    if (i < NN) { g_deg[i] = 1; g_cursor[i] = 0; }   // deg starts at 1 (self loop)
    if (blockIdx.x == 0) {
        __shared__ int s_ok;
        if (threadIdx.x == 0) s_ok = 1;
        __syncthreads();
        if (threadIdx.x < 64) {
            long long v = ((const long long*)ei)[threadIdx.x];
            if (v < 0 || v >= NN) atomicExch(&s_ok, 0);
        }
        __syncthreads();
        if (threadIdx.x == 0) g_is64 = s_ok;
    }
}

__device__ __forceinline__ int get_idx(const void* __restrict__ ei, int pos) {
    if (g_is64) return (int)((const long long*)ei)[pos];
    return ((const int*)ei)[pos];
}

// ---------------------------------------------------------------------------
// CSR build
// ---------------------------------------------------------------------------
__global__ void k_count(const void* __restrict__ ei) {
    int e = blockIdx.x * blockDim.x + threadIdx.x;
    if (e < NE) atomicAdd(&g_deg[get_idx(ei, NE + e)], 1);
}

__global__ void k_scan_a() {
    int base = blockIdx.x * 1024;
    int s = 0;
    for (int j = threadIdx.x; j < 1024; j += 256) {
        int i = base + j;
        if (i < NN) s += g_deg[i] - 1;
    }
    #pragma unroll
    for (int m = 16; m; m >>= 1) s += __shfl_xor_sync(0xffffffffu, s, m);
    __shared__ int wsum[8];
    if ((threadIdx.x & 31) == 0) wsum[threadIdx.x >> 5] = s;
    __syncthreads();
    if (threadIdx.x == 0) {
        int t = 0;
        #pragma unroll
        for (int w = 0; w < 8; w++) t += wsum[w];
        g_csum[blockIdx.x] = t;
    }
}

__global__ void k_scan_c() {
    __shared__ int sm[1024];
    __shared__ int carry;
    int b = blockIdx.x;
    if (threadIdx.x == 0) {
        int run = 0;
        for (int j = 0; j < b; j++) run += g_csum[j];
        carry = run;
    }
    int i = b * 1024 + threadIdx.x;
    int deg = (i < NN) ? g_deg[i] : 1;
    int v = (i < NN) ? deg - 1 : 0;
    sm[threadIdx.x] = v;
    __syncthreads();
    for (int off = 1; off < 1024; off <<= 1) {
        int t = (threadIdx.x >= off) ? sm[threadIdx.x - off] : 0;
        __syncthreads();
        sm[threadIdx.x] += t;
        __syncthreads();
    }
    if (i < NN) {
        g_off[i]  = carry + sm[threadIdx.x] - v;
        g_dinv[i] = rsqrtf((float)deg);
    }
    if (b == NCHUNK - 1 && threadIdx.x == 1023) g_off[NN] = carry + sm[1023];
}

__global__ void k_fill(const void* __restrict__ ei) {
    int e = blockIdx.x * blockDim.x + threadIdx.x;
    if (e < NE) {
        int src = get_idx(ei, e);
        int dst = get_idx(ei, NE + e);
        int p = atomicAdd(&g_cursor[dst], 1);
        g_srcs[g_off[dst] + p] = src;
    }
}

// ===========================================================================
// GEMM: g_h = x @ W^T, tf32 wmma (m16n16k8). Block tile 128x128 with
// 512 threads = 16 warps in a 4x4 grid of 32x32 warp tiles. 64 regs/thread
// (accums 32 + frags 16) -> 2 CTAs/SM = 32 warps/SM (occ 50%, was 25%):
// the R10 profile showed occ=23%/issue=23%/tensor=42% with nothing
// saturated, i.e. latency-bound on LDS->HMMA chains. Doubling resident
// warps targets tensor ~70%+. 3-stage cp.async pipeline unchanged.
// ===========================================================================
#define KCH   32
#define SLD   36                 // smem leading dim (floats): 4-bank row skew
#define STG   (128 * SLD)        // floats per operand-stage
#define GEMM_SMEM (6 * STG * 4)  // 3 stages x 2 operands = 110592 B

__device__ __forceinline__ void cpa16(float* dst, const float* src, bool pred) {
    unsigned d = (unsigned)__cvta_generic_to_shared(dst);
    int sz = pred ? 16 : 0;
    asm volatile("cp.async.cg.shared.global [%0], [%1], 16, %2;\n"
                 :: "r"(d), "l"(src), "r"(sz));
}
#define CP_COMMIT() asm volatile("cp.async.commit_group;\n")
#define CP_WAIT(n)  asm volatile("cp.async.wait_group %0;\n" :: "n"(n))

extern __shared__ float smem_dyn[];

__global__ __launch_bounds__(512, 2) void k_gemm(const float* __restrict__ x,
                                                 const float* __restrict__ Wm) {
    int tid = threadIdx.x;
    int n0 = blockIdx.x * 128;      // fast dim: both N-halves adjacent bids
    int r0 = blockIdx.y * 128;
    int w  = tid >> 5;
    int wm = w & 3;        // 4 warps along M (32 rows each)
    int wn = w >> 2;       // 4 warps along N (32 cols each)

    wmma::fragment<wmma::accumulator, 16, 16, 8, float> c[2][2];
    #pragma unroll
    for (int i = 0; i < 2; i++)
        #pragma unroll
        for (int j = 0; j < 2; j++) wmma::fill_fragment(c[i][j], 0.0f);

    auto load_chunk = [&](int ch) {
        int st = ch % 3;
        int kc = ch * KCH;
        float* xb = smem_dyn + st * STG;
        float* wb = smem_dyn + (3 + st) * STG;
        #pragma unroll
        for (int it = 0; it < 2; it++) {
            int t = it * 512 + tid;
            int row = t >> 3, q = t & 7;          // 8 float4 = 32 floats per row
            cpa16(xb + row * SLD + q * 4, x + (size_t)(r0 + row) * WD + kc + q * 4,
                  (r0 + row) < NN);
            cpa16(wb + row * SLD + q * 4, Wm + (size_t)(n0 + row) * WD + kc + q * 4,
                  true);
        }
        CP_COMMIT();
    };

    load_chunk(0);
    load_chunk(1);
    for (int ch = 0; ch < 8; ch++) {
        if (ch + 2 < 8) load_chunk(ch + 2);
        if (ch < 6) CP_WAIT(2);
        else if (ch == 6) CP_WAIT(1);
        else CP_WAIT(0);
        __syncthreads();

        float* xb = smem_dyn + (ch % 3) * STG;
        float* wb = smem_dyn + (3 + ch % 3) * STG;
        #pragma unroll
        for (int kk = 0; kk < KCH; kk += 8) {
            wmma::fragment<wmma::matrix_a, 16, 16, 8, wmma::precision::tf32, wmma::row_major> a[2];
            wmma::fragment<wmma::matrix_b, 16, 16, 8, wmma::precision::tf32, wmma::col_major> bf[2];
            #pragma unroll
            for (int i = 0; i < 2; i++)
                wmma::load_matrix_sync(a[i], xb + (wm * 32 + i * 16) * SLD + kk, SLD);
            #pragma unroll
            for (int j = 0; j < 2; j++)
                wmma::load_matrix_sync(bf[j], wb + (wn * 32 + j * 16) * SLD + kk, SLD);
            // no __float_to_tf32: HW truncates the container's low mantissa bits
            #pragma unroll
            for (int i = 0; i < 2; i++)
                #pragma unroll
                for (int j = 0; j < 2; j++)
                    wmma::mma_sync(c[i][j], a[i], bf[j], c[i][j]);
        }
        __syncthreads();   // stage ch%3 reloaded at iter ch+1 (chunk ch+3)
    }
    #pragma unroll
    for (int i = 0; i < 2; i++)
        #pragma unroll
        for (int j = 0; j < 2; j++) {
            float* dst = g_h + (size_t)(r0 + wm * 32 + i * 16) * WD + n0 + wn * 32 + j * 16;
            wmma::store_matrix_sync(dst, c[i][j], WD, wmma::mem_row_major);
        }
}

// ---------------------------------------------------------------------------
// Gather + bias + LayerNorm + ReLU. One WARP per node (32 lanes x 8 floats).
// out[d] = relu( LN( dinv[d]*(sum_e dinv[s]*h[s] + dinv[d]*h[d]) + b ) )
// ---------------------------------------------------------------------------
__global__ __launch_bounds__(256) void k_agg(const float* __restrict__ bias,
                                             const float* __restrict__ gamma,
                                             const float* __restrict__ beta,
                                             float* __restrict__ out) {
    int lane = threadIdx.x & 31;
    int node = blockIdx.x * 8 + (threadIdx.x >> 5);   // 6250 * 8 = 50000 exact
    const float4* h4 = (const float4*)g_h;

    float di = g_dinv[node];
    float4 a0 = h4[(size_t)node * 64 + lane];
    float4 a1 = h4[(size_t)node * 64 + 32 + lane];
    a0.x *= di; a0.y *= di; a0.z *= di; a0.w *= di;
    a1.x *= di; a1.y *= di; a1.z *= di; a1.w *= di;

    int e0 = g_off[node], e1 = g_off[node + 1];
    #pragma unroll 2
    for (int e = e0; e < e1; e++) {
        int sn = g_srcs[e];
        float ds = g_dinv[sn];
        float4 v0 = h4[(size_t)sn * 64 + lane];
        float4 v1 = h4[(size_t)sn * 64 + 32 + lane];
        a0.x = fmaf(ds, v0.x, a0.x); a0.y = fmaf(ds, v0.y, a0.y);
        a0.z = fmaf(ds, v0.z, a0.z); a0.w = fmaf(ds, v0.w, a0.w);
        a1.x = fmaf(ds, v1.x, a1.x); a1.y = fmaf(ds, v1.y, a1.y);
        a1.z = fmaf(ds, v1.z, a1.z); a1.w = fmaf(ds, v1.w, a1.w);
    }

    const float4* b4 = (const float4*)bias;
    float4 bb0 = b4[lane], bb1 = b4[32 + lane];
    float4 p0, p1;
    p0.x = fmaf(di, a0.x, bb0.x); p0.y = fmaf(di, a0.y, bb0.y);
    p0.z = fmaf(di, a0.z, bb0.z); p0.w = fmaf(di, a0.w, bb0.w);
    p1.x = fmaf(di, a1.x, bb1.x); p1.y = fmaf(di, a1.y, bb1.y);
    p1.z = fmaf(di, a1.z, bb1.z); p1.w = fmaf(di, a1.w, bb1.w);

    float s1 = p0.x + p0.y + p0.z + p0.w + p1.x + p1.y + p1.z + p1.w;
    float s2 = p0.x * p0.x + p0.y * p0.y + p0.z * p0.z + p0.w * p0.w
             + p1.x * p1.x + p1.y * p1.y + p1.z * p1.z + p1.w * p1.w;
    #pragma unroll
    for (int m = 16; m; m >>= 1) {
        s1 += __shfl_xor_sync(0xffffffffu, s1, m);
        s2 += __shfl_xor_sync(0xffffffffu, s2, m);
    }
    float mean = s1 * (1.0f / 256.0f);
    float var  = s2 * (1.0f / 256.0f) - mean * mean;
    float rstd = rsqrtf(var + 1e-5f);

    const float4* g4  = (const float4*)gamma;
    const float4* be4 = (const float4*)beta;
    float4 gg0 = g4[lane], gg1 = g4[32 + lane];
    float4 bt0 = be4[lane], bt1 = be4[32 + lane];
    float4 o0, o1;
    o0.x = fmaxf(0.f, fmaf((p0.x - mean) * rstd, gg0.x, bt0.x));
    o0.y = fmaxf(0.f, fmaf((p0.y - mean) * rstd, gg0.y, bt0.y));
    o0.z = fmaxf(0.f, fmaf((p0.z - mean) * rstd, gg0.z, bt0.z));
    o0.w = fmaxf(0.f, fmaf((p0.w - mean) * rstd, gg0.w, bt0.w));
    o1.x = fmaxf(0.f, fmaf((p1.x - mean) * rstd, gg1.x, bt1.x));
    o1.y = fmaxf(0.f, fmaf((p1.y - mean) * rstd, gg1.y, bt1.y));
    o1.z = fmaxf(0.f, fmaf((p1.z - mean) * rstd, gg1.z, bt1.z));
    o1.w = fmaxf(0.f, fmaf((p1.w - mean) * rstd, gg1.w, bt1.w));
    ((float4*)out)[(size_t)node * 64 + lane]      = o0;
    ((float4*)out)[(size_t)node * 64 + 32 + lane] = o1;
}

// ---------------------------------------------------------------------------
// Fork/join: CSR chain (side stream) concurrent with GEMM (main stream).
// Issue order puts k_gemm 4th — ncu's window profiles the 4th kernel launch.
// ---------------------------------------------------------------------------
extern "C" void kernel_launch(void* const* d_in, const int* in_sizes, int n_in,
                              void* d_out, int out_size) {
    const float* x     = (const float*)d_in[0];
    const void*  ei    = d_in[1];
    const float* Wm    = (const float*)d_in[2];
    const float* bias  = (const float*)d_in[3];
    const float* gamma = (const float*)d_in[4];
    const float* beta  = (const float*)d_in[5];
    float* out = (float*)d_out;

    static cudaStream_t s2;
    static cudaEvent_t evFork, evJoin;
    static bool inited = false;
    if (!inited) {
        cudaFuncSetAttribute(k_gemm, cudaFuncAttributeMaxDynamicSharedMemorySize,
                             GEMM_SMEM);
        cudaStreamCreateWithFlags(&s2, cudaStreamNonBlocking);
        cudaEventCreateWithFlags(&evFork, cudaEventDisableTiming);
        cudaEventCreateWithFlags(&evJoin, cudaEventDisableTiming);
        inited = true;
    }

    // fork: side stream depends on everything already in the main stream
    cudaEventRecord(evFork, 0);
    cudaStreamWaitEvent(s2, evFork, 0);

    // CSR branch starts (side stream): launches 1-3
    k_init<<<(NN + 255) / 256, 256, 0, s2>>>(ei);
    k_count<<<(NE + 255) / 256, 256, 0, s2>>>(ei);
    k_scan_a<<<NCHUNK, 256, 0, s2>>>();

    // GEMM branch (main stream): 4th kernel launch in issue order
    k_gemm<<<dim3(2, 391), 512, GEMM_SMEM>>>(x, Wm);

    // CSR branch continues (side stream)
    k_scan_c<<<NCHUNK, 1024, 0, s2>>>();
    k_fill<<<(NE + 255) / 256, 256, 0, s2>>>(ei);
    cudaEventRecord(evJoin, s2);

    // join, then fused gather+LN+ReLU
    cudaStreamWaitEvent(0, evJoin, 0);
    k_agg<<<NN / 8, 256>>>(bias, gamma, beta, out);
}

// round 16
// speedup vs baseline: 1.1148x; 1.1148x over previous
#include <cuda_runtime.h>
#include <mma.h>
#include <cstdint>

using namespace nvcuda;

#define NN 50000
#define NE 312500
#define WD 256
#define MROWS 50048          // 391 * 128
#define NCHUNK 49            // ceil(50000/1024)

// ---- scratch (device globals; no allocation allowed) ----
__device__ int   g_deg[NN];
__device__ int   g_cursor[NN];
__device__ float g_dinv[NN];
__device__ int   g_off[NN + 1];
__device__ int   g_srcs[NE];
__device__ float g_h[MROWS * WD];     // h = x @ W^T, 51.2 MB — L2-resident
__device__ int   g_csum[NCHUNK];
__device__ int   g_is64;

// ---------------------------------------------------------------------------
// init + index-dtype detection (reference declares int64 edge_index; JAX
// without x64 silently emits int32 — 64 in-range int64 reads are conclusive)
// ---------------------------------------------------------------------------
__global__ void k_init(const void* __restrict__ ei) {
    int i = blockIdx.x * blockDim.x + threadIdx.x;
    if (i < NN) { g_deg[i] = 1; g_cursor[i] = 0; }   // deg starts at 1 (self loop)
    if (blockIdx.x == 0) {
        __shared__ int s_ok;
        if (threadIdx.x == 0) s_ok = 1;
        __syncthreads();
        if (threadIdx.x < 64) {
            long long v = ((const long long*)ei)[threadIdx.x];
            if (v < 0 || v >= NN) atomicExch(&s_ok, 0);
        }
        __syncthreads();
        if (threadIdx.x == 0) g_is64 = s_ok;
    }
}

__device__ __forceinline__ int get_idx(const void* __restrict__ ei, int pos) {
    if (g_is64) return (int)((const long long*)ei)[pos];
    return ((const int*)ei)[pos];
}

// ---------------------------------------------------------------------------
// CSR build
// ---------------------------------------------------------------------------
__global__ void k_count(const void* __restrict__ ei) {
    int e = blockIdx.x * blockDim.x + threadIdx.x;
    if (e < NE) atomicAdd(&g_deg[get_idx(ei, NE + e)], 1);
}

__global__ void k_scan_a() {
    int base = blockIdx.x * 1024;
    int s = 0;
    for (int j = threadIdx.x; j < 1024; j += 256) {
        int i = base + j;
        if (i < NN) s += g_deg[i] - 1;
    }
    #pragma unroll
    for (int m = 16; m; m >>= 1) s += __shfl_xor_sync(0xffffffffu, s, m);
    __shared__ int wsum[8];
    if ((threadIdx.x & 31) == 0) wsum[threadIdx.x >> 5] = s;
    __syncthreads();
    if (threadIdx.x == 0) {
        int t = 0;
        #pragma unroll
        for (int w = 0; w < 8; w++) t += wsum[w];
        g_csum[blockIdx.x] = t;
    }
}

__global__ void k_scan_c() {
    __shared__ int sm[1024];
    __shared__ int carry;
    int b = blockIdx.x;
    if (threadIdx.x == 0) {
        int run = 0;
        for (int j = 0; j < b; j++) run += g_csum[j];
        carry = run;
    }
    int i = b * 1024 + threadIdx.x;
    int deg = (i < NN) ? g_deg[i] : 1;
    int v = (i < NN) ? deg - 1 : 0;
    sm[threadIdx.x] = v;
    __syncthreads();
    for (int off = 1; off < 1024; off <<= 1) {
        int t = (threadIdx.x >= off) ? sm[threadIdx.x - off] : 0;
        __syncthreads();
        sm[threadIdx.x] += t;
        __syncthreads();
    }
    if (i < NN) {
        g_off[i]  = carry + sm[threadIdx.x] - v;
        g_dinv[i] = rsqrtf((float)deg);
    }
    if (b == NCHUNK - 1 && threadIdx.x == 1023) g_off[NN] = carry + sm[1023];
}

__global__ void k_fill(const void* __restrict__ ei) {
    int e = blockIdx.x * blockDim.x + threadIdx.x;
    if (e < NE) {
        int src = get_idx(ei, e);
        int dst = get_idx(ei, NE + e);
        int p = atomicAdd(&g_cursor[dst], 1);
        g_srcs[g_off[dst] + p] = src;
    }
}

// ===========================================================================
// GEMM: g_h = x @ W^T, tf32 wmma (m16n16k8). Block tile 128x128 with
// 4 warps (128 threads) in a 2x2 grid of 64x64 warp tiles.
// R10 vs R14 showed tensor-busy time is FIXED (43us) and perf tracks
// fragment-load traffic per MMA (R10 0.75 loads/MMA = 101us; R14 1.0 = 114us).
// 64x64 tiles give 0.5 loads/MMA: 8 frag loads feed 16 MMAs per k-step.
// ~200-230 regs/thread (16 accum + 8 operand frags), launch_bounds(128,2)
// -> 2 CTAs/SM, smem 2x110.6KB fits. 3-stage cp.async pipeline unchanged.
// ===========================================================================
#define KCH   32
#define SLD   36                 // smem leading dim (floats): 4-bank row skew
#define STG   (128 * SLD)        // floats per operand-stage
#define GEMM_SMEM (6 * STG * 4)  // 3 stages x 2 operands = 110592 B

__device__ __forceinline__ void cpa16(float* dst, const float* src, bool pred) {
    unsigned d = (unsigned)__cvta_generic_to_shared(dst);
    int sz = pred ? 16 : 0;
    asm volatile("cp.async.cg.shared.global [%0], [%1], 16, %2;\n"
                 :: "r"(d), "l"(src), "r"(sz));
}
#define CP_COMMIT() asm volatile("cp.async.commit_group;\n")
#define CP_WAIT(n)  asm volatile("cp.async.wait_group %0;\n" :: "n"(n))

extern __shared__ float smem_dyn[];

__global__ __launch_bounds__(128, 2) void k_gemm(const float* __restrict__ x,
                                                 const float* __restrict__ Wm) {
    int tid = threadIdx.x;
    int n0 = blockIdx.x * 128;      // fast dim: both N-halves adjacent bids
    int r0 = blockIdx.y * 128;
    int w  = tid >> 5;
    int wm = w & 1;        // 2 warps along M (64 rows each)
    int wn = w >> 1;       // 2 warps along N (64 cols each)

    wmma::fragment<wmma::accumulator, 16, 16, 8, float> c[4][4];
    #pragma unroll
    for (int i = 0; i < 4; i++)
        #pragma unroll
        for (int j = 0; j < 4; j++) wmma::fill_fragment(c[i][j], 0.0f);

    auto load_chunk = [&](int ch) {
        int st = ch % 3;
        int kc = ch * KCH;
        float* xb = smem_dyn + st * STG;
        float* wb = smem_dyn + (3 + st) * STG;
        #pragma unroll
        for (int it = 0; it < 8; it++) {
            int t = it * 128 + tid;
            int row = t >> 3, q = t & 7;          // 8 float4 = 32 floats per row
            cpa16(xb + row * SLD + q * 4, x + (size_t)(r0 + row) * WD + kc + q * 4,
                  (r0 + row) < NN);
            cpa16(wb + row * SLD + q * 4, Wm + (size_t)(n0 + row) * WD + kc + q * 4,
                  true);
        }
        CP_COMMIT();
    };

    load_chunk(0);
    load_chunk(1);
    for (int ch = 0; ch < 8; ch++) {
        if (ch + 2 < 8) load_chunk(ch + 2);
        if (ch < 6) CP_WAIT(2);
        else if (ch == 6) CP_WAIT(1);
        else CP_WAIT(0);
        __syncthreads();

        float* xb = smem_dyn + (ch % 3) * STG;
        float* wb = smem_dyn + (3 + ch % 3) * STG;
        #pragma unroll
        for (int kk = 0; kk < KCH; kk += 8) {
            wmma::fragment<wmma::matrix_a, 16, 16, 8, wmma::precision::tf32, wmma::row_major> a[4];
            wmma::fragment<wmma::matrix_b, 16, 16, 8, wmma::precision::tf32, wmma::col_major> bf[4];
            #pragma unroll
            for (int i = 0; i < 4; i++)
                wmma::load_matrix_sync(a[i], xb + (wm * 64 + i * 16) * SLD + kk, SLD);
            #pragma unroll
            for (int j = 0; j < 4; j++)
                wmma::load_matrix_sync(bf[j], wb + (wn * 64 + j * 16) * SLD + kk, SLD);
            // no __float_to_tf32: HW truncates the container's low mantissa bits
            #pragma unroll
            for (int i = 0; i < 4; i++)
                #pragma unroll
                for (int j = 0; j < 4; j++)
                    wmma::mma_sync(c[i][j], a[i], bf[j], c[i][j]);
        }
        __syncthreads();   // stage ch%3 reloaded at iter ch+1 (chunk ch+3)
    }
    #pragma unroll
    for (int i = 0; i < 4; i++)
        #pragma unroll
        for (int j = 0; j < 4; j++) {
            float* dst = g_h + (size_t)(r0 + wm * 64 + i * 16) * WD + n0 + wn * 64 + j * 16;
            wmma::store_matrix_sync(dst, c[i][j], WD, wmma::mem_row_major);
        }
}

// ---------------------------------------------------------------------------
// Gather + bias + LayerNorm + ReLU. One WARP per node (32 lanes x 8 floats).
// out[d] = relu( LN( dinv[d]*(sum_e dinv[s]*h[s] + dinv[d]*h[d]) + b ) )
// ---------------------------------------------------------------------------
__global__ __launch_bounds__(256) void k_agg(const float* __restrict__ bias,
                                             const float* __restrict__ gamma,
                                             const float* __restrict__ beta,
                                             float* __restrict__ out) {
    int lane = threadIdx.x & 31;
    int node = blockIdx.x * 8 + (threadIdx.x >> 5);   // 6250 * 8 = 50000 exact
    const float4* h4 = (const float4*)g_h;

    float di = g_dinv[node];
    float4 a0 = h4[(size_t)node * 64 + lane];
    float4 a1 = h4[(size_t)node * 64 + 32 + lane];
    a0.x *= di; a0.y *= di; a0.z *= di; a0.w *= di;
    a1.x *= di; a1.y *= di; a1.z *= di; a1.w *= di;

    int e0 = g_off[node], e1 = g_off[node + 1];
    #pragma unroll 2
    for (int e = e0; e < e1; e++) {
        int sn = g_srcs[e];
        float ds = g_dinv[sn];
        float4 v0 = h4[(size_t)sn * 64 + lane];
        float4 v1 = h4[(size_t)sn * 64 + 32 + lane];
        a0.x = fmaf(ds, v0.x, a0.x); a0.y = fmaf(ds, v0.y, a0.y);
        a0.z = fmaf(ds, v0.z, a0.z); a0.w = fmaf(ds, v0.w, a0.w);
        a1.x = fmaf(ds, v1.x, a1.x); a1.y = fmaf(ds, v1.y, a1.y);
        a1.z = fmaf(ds, v1.z, a1.z); a1.w = fmaf(ds, v1.w, a1.w);
    }

    const float4* b4 = (const float4*)bias;
    float4 bb0 = b4[lane], bb1 = b4[32 + lane];
    float4 p0, p1;
    p0.x = fmaf(di, a0.x, bb0.x); p0.y = fmaf(di, a0.y, bb0.y);
    p0.z = fmaf(di, a0.z, bb0.z); p0.w = fmaf(di, a0.w, bb0.w);
    p1.x = fmaf(di, a1.x, bb1.x); p1.y = fmaf(di, a1.y, bb1.y);
    p1.z = fmaf(di, a1.z, bb1.z); p1.w = fmaf(di, a1.w, bb1.w);

    float s1 = p0.x + p0.y + p0.z + p0.w + p1.x + p1.y + p1.z + p1.w;
    float s2 = p0.x * p0.x + p0.y * p0.y + p0.z * p0.z + p0.w * p0.w
             + p1.x * p1.x + p1.y * p1.y + p1.z * p1.z + p1.w * p1.w;
    #pragma unroll
    for (int m = 16; m; m >>= 1) {
        s1 += __shfl_xor_sync(0xffffffffu, s1, m);
        s2 += __shfl_xor_sync(0xffffffffu, s2, m);
    }
    float mean = s1 * (1.0f / 256.0f);
    float var  = s2 * (1.0f / 256.0f) - mean * mean;
    float rstd = rsqrtf(var + 1e-5f);

    const float4* g4  = (const float4*)gamma;
    const float4* be4 = (const float4*)beta;
    float4 gg0 = g4[lane], gg1 = g4[32 + lane];
    float4 bt0 = be4[lane], bt1 = be4[32 + lane];
    float4 o0, o1;
    o0.x = fmaxf(0.f, fmaf((p0.x - mean) * rstd, gg0.x, bt0.x));
    o0.y = fmaxf(0.f, fmaf((p0.y - mean) * rstd, gg0.y, bt0.y));
    o0.z = fmaxf(0.f, fmaf((p0.z - mean) * rstd, gg0.z, bt0.z));
    o0.w = fmaxf(0.f, fmaf((p0.w - mean) * rstd, gg0.w, bt0.w));
    o1.x = fmaxf(0.f, fmaf((p1.x - mean) * rstd, gg1.x, bt1.x));
    o1.y = fmaxf(0.f, fmaf((p1.y - mean) * rstd, gg1.y, bt1.y));
    o1.z = fmaxf(0.f, fmaf((p1.z - mean) * rstd, gg1.z, bt1.z));
    o1.w = fmaxf(0.f, fmaf((p1.w - mean) * rstd, gg1.w, bt1.w));
    ((float4*)out)[(size_t)node * 64 + lane]      = o0;
    ((float4*)out)[(size_t)node * 64 + 32 + lane] = o1;
}

// ---------------------------------------------------------------------------
// Fork/join: CSR chain (side stream) concurrent with GEMM (main stream).
// Issue order puts k_gemm 4th — ncu's window profiles the 4th kernel launch.
// ---------------------------------------------------------------------------
extern "C" void kernel_launch(void* const* d_in, const int* in_sizes, int n_in,
                              void* d_out, int out_size) {
    const float* x     = (const float*)d_in[0];
    const void*  ei    = d_in[1];
    const float* Wm    = (const float*)d_in[2];
    const float* bias  = (const float*)d_in[3];
    const float* gamma = (const float*)d_in[4];
    const float* beta  = (const float*)d_in[5];
    float* out = (float*)d_out;

    static cudaStream_t s2;
    static cudaEvent_t evFork, evJoin;
    static bool inited = false;
    if (!inited) {
        cudaFuncSetAttribute(k_gemm, cudaFuncAttributeMaxDynamicSharedMemorySize,
                             GEMM_SMEM);
        cudaStreamCreateWithFlags(&s2, cudaStreamNonBlocking);
        cudaEventCreateWithFlags(&evFork, cudaEventDisableTiming);
        cudaEventCreateWithFlags(&evJoin, cudaEventDisableTiming);
        inited = true;
    }

    // fork: side stream depends on everything already in the main stream
    cudaEventRecord(evFork, 0);
    cudaStreamWaitEvent(s2, evFork, 0);

    // CSR branch starts (side stream): launches 1-3
    k_init<<<(NN + 255) / 256, 256, 0, s2>>>(ei);
    k_count<<<(NE + 255) / 256, 256, 0, s2>>>(ei);
    k_scan_a<<<NCHUNK, 256, 0, s2>>>();

    // GEMM branch (main stream): 4th kernel launch in issue order
    k_gemm<<<dim3(2, 391), 128, GEMM_SMEM>>>(x, Wm);

    // CSR branch continues (side stream)
    k_scan_c<<<NCHUNK, 1024, 0, s2>>>();
    k_fill<<<(NE + 255) / 256, 256, 0, s2>>>(ei);
    cudaEventRecord(evJoin, s2);

    // join, then fused gather+LN+ReLU
    cudaStreamWaitEvent(0, evJoin, 0);
    k_agg<<<NN / 8, 256>>>(bias, gamma, beta, out);
}